// round 11
// baseline (speedup 1.0000x reference)
#include <cuda_runtime.h>
#include <cuda_fp16.h>
#include <cstdint>

#define DI __device__ __forceinline__

// ---------------- problem constants ----------------
namespace {
constexpr int BATCH = 128;
constexpr int NFRM  = 16;
constexpr int TPF   = 49;
constexpr int NSEL  = 8;
constexpr int TOK   = NFRM * TPF;          // 784
constexpr int MTOT  = BATCH * TOK;         // 100352
constexpr int KDIM  = 1024;
constexpr int NDIM  = 512;

constexpr int M_TILE = 128;
constexpr int N_TILE = 256;
constexpr int KC     = 64;                 // fp16 elems per K-chunk (=128B row)
constexpr int NK     = KDIM / KC;          // 16
constexpr int NCOMP  = 256;                // 8 compute warps: 2(m) x 4(n), 64x64
constexpr int NTHR   = 384;                // + 4 loader warps (128 threads)
constexpr long long SEL_ELEMS = (long long)BATCH * NSEL * TPF * NDIM; // 25,690,112

// shared memory: 3 A stages (16KB), 2 B stages (32KB), bias
constexpr int A_STAGE  = 16384;
constexpr int SM_B0    = 3 * A_STAGE;      // 49152
constexpr int B_STAGE  = 32768;
constexpr int SM_BIAS  = SM_B0 + 2 * B_STAGE;   // 114688
constexpr int SM_TOTAL = SM_BIAS + 1024;        // 115712
}

// ---------------- device scratch (no runtime allocation allowed) -----------
__device__ __half g_vid[(size_t)MTOT * NDIM];    // 102.8 MB vid_feats (fp16)
__device__ __half g_wth[NDIM * KDIM];            // fc_w transposed, fp16
__device__ float  g_part[2][MTOT];               // per-n-block sumsq partials

// ---------------- PTX helpers ----------------
DI uint32_t smem_u32(const void* p) {
    uint32_t a;
    asm("{ .reg .u64 t; cvta.to.shared.u64 t, %1; cvt.u32.u64 %0, t; }" : "=r"(a) : "l"(p));
    return a;
}
DI void ldsm4(uint32_t (&r)[4], uint32_t addr) {
    asm volatile("ldmatrix.sync.aligned.m8n8.x4.shared.b16 {%0,%1,%2,%3}, [%4];"
                 : "=r"(r[0]), "=r"(r[1]), "=r"(r[2]), "=r"(r[3]) : "r"(addr));
}
DI void mma16(float (&d)[4], const uint32_t (&a)[4], uint32_t b0, uint32_t b1) {
    asm volatile("mma.sync.aligned.m16n8k16.row.col.f32.f16.f16.f32 "
                 "{%0,%1,%2,%3}, {%4,%5,%6,%7}, {%8,%9}, {%0,%1,%2,%3};"
                 : "+f"(d[0]), "+f"(d[1]), "+f"(d[2]), "+f"(d[3])
                 : "r"(a[0]), "r"(a[1]), "r"(a[2]), "r"(a[3]), "r"(b0), "r"(b1));
}
DI void cp16(uint32_t dst, const void* src) {
    asm volatile("cp.async.cg.shared.global [%0], [%1], 16;" :: "r"(dst), "l"(src) : "memory");
}
#define CP_COMMIT() asm volatile("cp.async.commit_group;" ::: "memory")
#define CP_WAIT0()  asm volatile("cp.async.wait_group 0;" ::: "memory")

// ---------------- kernel 1: transpose + fp16-round fc_w (tiny) -------------
__global__ void wt_kernel(const float* __restrict__ w) {
    __shared__ float t[32][33];
    int k0 = blockIdx.x * 32, n0 = blockIdx.y * 32;
    int x = threadIdx.x, y = threadIdx.y;
    #pragma unroll
    for (int dy = 0; dy < 32; dy += 8)
        t[y + dy][x] = w[(size_t)(k0 + y + dy) * NDIM + n0 + x];
    __syncthreads();
    #pragma unroll
    for (int dy = 0; dy < 32; dy += 8)
        g_wth[(size_t)(n0 + y + dy) * KDIM + k0 + x] = __float2half_rn(t[x][y + dy]);
}

// ---------------- kernel 2: fused-cvt fp16 GEMM, 3-stage A loader ----------
// Loader warps (128 threads): A chunk = 128 rows x 64 f16 (16KB) from f32
// source (32KB). 8 slots/thread, 16 LDG.128 in flight, ~900 cyc/chunk.
DI void loader_fill_A(const float* __restrict__ swin, char* abuf,
                      int m0, int kb, int lt) {
    const float* asrc = swin + (size_t)m0 * KDIM + kb;
    #pragma unroll
    for (int s = 0; s < 8; s++) {
        int slot = lt + s * 128;
        int row = slot >> 3, q = slot & 7;
        const float* p = asrc + (size_t)row * KDIM + q * 8;
        float4 v0 = *(const float4*)p;
        float4 v1 = *(const float4*)(p + 4);
        __half2 h0 = __floats2half2_rn(v0.x, v0.y);
        __half2 h1 = __floats2half2_rn(v0.z, v0.w);
        __half2 h2 = __floats2half2_rn(v1.x, v1.y);
        __half2 h3 = __floats2half2_rn(v1.z, v1.w);
        uint4 o;
        o.x = *(uint32_t*)&h0; o.y = *(uint32_t*)&h1;
        o.z = *(uint32_t*)&h2; o.w = *(uint32_t*)&h3;
        *(uint4*)(abuf + row * 128 + (((uint32_t)q ^ (row & 7)) << 4)) = o;
    }
}
// B chunk: 256 rows x 64 f16 = 32KB = 2048 x 16B; 8 cp.async per compute thread
DI void issueB(uint32_t bb, int gn0, int kb, int tid) {
    const __half* bsrc = g_wth + (size_t)gn0 * KDIM + kb;
    #pragma unroll
    for (int s = 0; s < 8; s++) {
        int slot = tid + s * NCOMP;
        int row = slot >> 3, q = slot & 7;
        cp16(bb + row * 128 + (((uint32_t)q ^ (row & 7)) << 4),
             bsrc + (size_t)row * KDIM + q * 8);
    }
    CP_COMMIT();
}

__global__ void __launch_bounds__(NTHR, 1)
gemm_kernel(const float* __restrict__ swin, const float* __restrict__ fcb) {
    extern __shared__ char smem[];
    uint32_t sb = smem_u32(smem);
    int tid = threadIdx.x;
    int w = tid >> 5, l = tid & 31;
    bool is_comp = tid < NCOMP;
    int lt = tid - NCOMP;                    // loader lane 0..127
    int nb = blockIdx.x;
    int m0 = blockIdx.y * M_TILE;
    int gn0 = nb * N_TILE;
    int wm = (w >> 2) * 64;                  // warp m offset (0,64)
    int wn = (w & 3) * 64;                   // warp n offset (0,64,128,192)

    if (tid < N_TILE) *(float*)(smem + SM_BIAS + tid * 4) = fcb[gn0 + tid];

    // ---- prologue ----
    if (is_comp) {
        issueB(sb + SM_B0, gn0, 0, tid);     // B chunk 0 into B stage 0
        CP_WAIT0();
    } else {
        loader_fill_A(swin, smem, m0, 0, lt);              // A chunk 0 -> stage 0
        loader_fill_A(swin, smem + A_STAGE, m0, KC, lt);   // A chunk 1 -> stage 1
    }
    __syncthreads();

    if (!is_comp) {
        // loader loop: during compute of chunk i, fill A(i+2) into stage (i+2)%3.
        // Stage (i+2)%3 was last read at chunk i-1; the barrier ending chunk
        // i-1 (start of this iteration) makes the overwrite safe.
        for (int i = 0; i < NK; i++) {
            int c = i + 2;
            if (c < NK)
                loader_fill_A(swin, smem + (c % 3) * A_STAGE, m0, c * KC, lt);
            __syncthreads();
        }
        return;                              // Volta+ barriers ignore exited threads
    }

    // ---- compute warps ----
    float acc[4][8][4];
    #pragma unroll
    for (int mt = 0; mt < 4; mt++)
        #pragma unroll
        for (int nt = 0; nt < 8; nt++)
            #pragma unroll
            for (int j = 0; j < 4; j++) acc[mt][nt][j] = 0.f;

    // per-lane ldmatrix offsets (verified mapping)
    uint32_t lx   = (uint32_t)(l & 7);
    uint32_t apar = (uint32_t)(l >> 4);          // A k-half parity
    uint32_t bpar = (uint32_t)((l >> 3) & 1);    // B k-half parity
    uint32_t a_off[4], b_off[4];
    {
        uint32_t arow = (uint32_t)(wm + (l & 15));
        #pragma unroll
        for (int mt = 0; mt < 4; mt++) a_off[mt] = (arow + mt * 16) * 128u;
        uint32_t brow = (uint32_t)(wn + (l & 7) + ((l & 16) >> 1));
        #pragma unroll
        for (int g = 0; g < 4; g++) b_off[g] = (brow + g * 16) * 128u + SM_B0;
    }

    for (int i = 0; i < NK; i++) {
        if (i + 1 < NK)
            issueB(sb + SM_B0 + ((i + 1) & 1) * B_STAGE, gn0, (i + 1) * KC, tid);

        uint32_t ab = sb + (i % 3) * A_STAGE;
        uint32_t bsel = ((uint32_t)i & 1) * B_STAGE;
        #pragma unroll
        for (int ks = 0; ks < 4; ks++) {
            uint32_t ca = ((2u * ks + apar) ^ lx) << 4;
            uint32_t cb = ((2u * ks + bpar) ^ lx) << 4;
            uint32_t bfr[4][4];
            #pragma unroll
            for (int g = 0; g < 4; g++) ldsm4(bfr[g], sb + bsel + b_off[g] + cb);
            #pragma unroll
            for (int mt = 0; mt < 4; mt++) {
                uint32_t af[4];
                ldsm4(af, ab + a_off[mt] + ca);
                #pragma unroll
                for (int nt = 0; nt < 8; nt++)
                    mma16(acc[mt][nt], af,
                          bfr[nt >> 1][(nt & 1) * 2], bfr[nt >> 1][(nt & 1) * 2 + 1]);
            }
        }
        CP_WAIT0();                          // B(i+1) resident
        __syncthreads();                     // chunk boundary (loader + compute)
    }

    // ---- epilogue: bias, fp16 vid write, per-row sumsq ----
    // A stage 0 last read at chunk 15; the final loop barrier protects reuse.
    const float* sbias = (const float*)(smem + SM_BIAS);
    float* part = (float*)smem;              // [128][4]
    #pragma unroll
    for (int mt = 0; mt < 4; mt++) {
        int r0 = wm + mt * 16 + (l >> 2);
        float s0 = 0.f, s1 = 0.f;
        #pragma unroll
        for (int nt = 0; nt < 8; nt++) {
            int colL = wn + nt * 8 + (l & 3) * 2;
            float b0 = sbias[colL], b1 = sbias[colL + 1];
            float v0 = acc[mt][nt][0] + b0, v1 = acc[mt][nt][1] + b1;
            float v2 = acc[mt][nt][2] + b0, v3 = acc[mt][nt][3] + b1;
            s0 += v0 * v0 + v1 * v1;
            s1 += v2 * v2 + v3 * v3;
            size_t g0 = (size_t)(m0 + r0) * NDIM + gn0 + colL;
            *(__half2*)(g_vid + g0) = __floats2half2_rn(v0, v1);
            *(__half2*)(g_vid + g0 + 8 * NDIM) = __floats2half2_rn(v2, v3);
        }
        s0 += __shfl_xor_sync(0xFFFFFFFFu, s0, 1);
        s0 += __shfl_xor_sync(0xFFFFFFFFu, s0, 2);
        s1 += __shfl_xor_sync(0xFFFFFFFFu, s1, 1);
        s1 += __shfl_xor_sync(0xFFFFFFFFu, s1, 2);
        if ((l & 3) == 0) {
            part[r0 * 4 + (w & 3)] = s0;
            part[(r0 + 8) * 4 + (w & 3)] = s1;
        }
    }
    __syncthreads();
    if (tid < M_TILE) {
        float s = part[tid * 4] + part[tid * 4 + 1] + part[tid * 4 + 2] + part[tid * 4 + 3];
        g_part[nb][m0 + tid] = s;
    }
}

// ---------------- kernel 3: scores + selection + gather (fused) ------------
__global__ void post_kernel(const float* __restrict__ tscore,
                            const float* __restrict__ gumbel,
                            float* __restrict__ out, long long out_elems) {
    __shared__ float tsh[TOK];
    __shared__ float fsh[NFRM];
    __shared__ float gsh[NSEL * NFRM];
    __shared__ int   sels[NSEL];
    int b = blockIdx.x, t = threadIdx.x;     // 256 threads
    for (int i = t; i < TOK; i += 256) {
        int gt = b * TOK + i;
        float s = g_part[0][gt] + g_part[1][gt];
        tsh[i] = tscore[gt] * sqrtf(s);
    }
    if (t < NSEL * NFRM) {
        int s = t >> 4, f = t & 15;
        gsh[t] = gumbel[((size_t)s * BATCH + b) * NFRM + f];
    }
    __syncthreads();
    if (t < NFRM) {
        float s = 0.f;
        #pragma unroll
        for (int j = 0; j < TPF; j++) s += tsh[t * TPF + j];
        fsh[t] = s;
    }
    __syncthreads();
    if (t == 0) {
        const float NEG_INF = __int_as_float(0xff800000);
        float tot = 0.f;
        for (int f = 0; f < NFRM; f++) tot += fsh[f];
        float fs[NFRM], sc[NFRM], sel[NFRM];
        for (int f = 0; f < NFRM; f++) { fs[f] = fsh[f] / tot; sc[f] = fs[f]; sel[f] = 0.f; }
        for (int s = 0; s < NSEL; s++) {
            const float* g = gsh + s * NFRM;
            float best = NEG_INF; int bi = 0;
            for (int f = 0; f < NFRM; f++) {
                float v = (sel[f] > 0.f) ? NEG_INF : (sc[f] + g[f]);
                if (v > best) { best = v; bi = f; }   // strict > == first-max argmax
            }
            sel[bi] = 1.f; sc[bi] = 0.f;
        }
        float rest = 0.f;
        for (int f = 0; f < NFRM; f++) rest += fs[f] * (1.f - sel[f]);
        float label = (rest >= 0.5f) ? 1.f : 0.f;
        int c = 0;
        for (int f = 0; f < NFRM; f++)
            if (sel[f] > 0.f) sels[c++] = f;         // ascending
        if (out_elems >= SEL_ELEMS + BATCH + (long long)BATCH * NFRM) {
            out[SEL_ELEMS + b] = label;
            float* fsp = out + SEL_ELEMS + BATCH;
            for (int f = 0; f < NFRM; f++) fsp[b * NFRM + f] = sel[f];
        }
    }
    __syncthreads();

    // gather 8 selected frames: f16 -> f32
    constexpr int N8 = TPF * NDIM / 8;       // 3136 groups of 8 halves per frame
    for (int j = 0; j < NSEL; j++) {
        int f = sels[j];
        const __half* src = g_vid + ((size_t)b * TOK + (size_t)f * TPF) * NDIM;
        float* dst = out + ((size_t)b * (NSEL * TPF) + (size_t)j * TPF) * NDIM;
        for (int i = t; i < N8; i += 256) {
            uint4 h = *(const uint4*)(src + (size_t)i * 8);
            __half2 h0 = *(__half2*)&h.x, h1 = *(__half2*)&h.y;
            __half2 h2 = *(__half2*)&h.z, h3 = *(__half2*)&h.w;
            float2 f0 = __half22float2(h0), f1 = __half22float2(h1);
            float2 f2 = __half22float2(h2), f3 = __half22float2(h3);
            *(float4*)(dst + (size_t)i * 8)     = make_float4(f0.x, f0.y, f1.x, f1.y);
            *(float4*)(dst + (size_t)i * 8 + 4) = make_float4(f2.x, f2.y, f3.x, f3.y);
        }
    }
}

// ---------------- launch ----------------
extern "C" void kernel_launch(void* const* d_in, const int* in_sizes, int n_in,
                              void* d_out, int out_size) {
    const float* swin = (const float*)d_in[0];   // (128, 784, 1024)
    const float* fcw  = (const float*)d_in[1];   // (1024, 512)
    const float* fcb  = (const float*)d_in[2];   // (512,)
    const float* tsc  = (const float*)d_in[3];   // (128, 784)
    const float* gum  = (const float*)d_in[4];   // (8, 128, 16)
    float* out = (float*)d_out;

    cudaFuncSetAttribute(gemm_kernel, cudaFuncAttributeMaxDynamicSharedMemorySize, SM_TOTAL);

    wt_kernel<<<dim3(KDIM / 32, NDIM / 32), dim3(32, 8)>>>(fcw);
    gemm_kernel<<<dim3(NDIM / N_TILE, MTOT / M_TILE), NTHR, SM_TOTAL>>>(swin, fcb);
    post_kernel<<<BATCH, 256>>>(tsc, gum, out, (long long)out_size);
    (void)in_sizes; (void)n_in;
}

// round 12
// speedup vs baseline: 1.2192x; 1.2192x over previous
#include <cuda_runtime.h>
#include <cuda_fp16.h>
#include <cstdint>

#define DI __device__ __forceinline__

// ---------------- problem constants ----------------
namespace {
constexpr int BATCH = 128;
constexpr int NFRM  = 16;
constexpr int TPF   = 49;
constexpr int NSEL  = 8;
constexpr int TOK   = NFRM * TPF;          // 784
constexpr int MTOT  = BATCH * TOK;         // 100352
constexpr int KDIM  = 1024;
constexpr int NDIM  = 512;

constexpr int M_TILE = 128;
constexpr int N_TILE = 256;
constexpr int KC     = 64;                 // fp16 elems per K-chunk (=128B row)
constexpr int NK     = KDIM / KC;          // 16
constexpr int NCOMP  = 256;                // 8 compute warps: 2(m) x 4(n), 64x64
constexpr int NTHR   = 384;                // + 4 loader warps (128 threads)
constexpr long long SEL_ELEMS = (long long)BATCH * NSEL * TPF * NDIM; // 25,690,112

// shared memory: 2 A stages (16KB), 2 B stages (32KB), bias
constexpr int A_STAGE  = 16384;
constexpr int SM_B0    = 2 * A_STAGE;      // 32768
constexpr int B_STAGE  = 32768;
constexpr int SM_BIAS  = SM_B0 + 2 * B_STAGE;   // 98304
constexpr int SM_TOTAL = SM_BIAS + 1024;        // 99328
}

// ---------------- device scratch (no runtime allocation allowed) -----------
__device__ __half g_vid[(size_t)MTOT * NDIM];    // 102.8 MB vid_feats (fp16)
__device__ __half g_wth[NDIM * KDIM];            // fc_w transposed, fp16
__device__ float  g_part[2][MTOT];               // per-n-block sumsq partials
__device__ int    g_sel[BATCH * NSEL];           // selected frames, ascending

// ---------------- PTX helpers ----------------
DI uint32_t smem_u32(const void* p) {
    uint32_t a;
    asm("{ .reg .u64 t; cvta.to.shared.u64 t, %1; cvt.u32.u64 %0, t; }" : "=r"(a) : "l"(p));
    return a;
}
DI void ldsm4(uint32_t (&r)[4], uint32_t addr) {
    asm volatile("ldmatrix.sync.aligned.m8n8.x4.shared.b16 {%0,%1,%2,%3}, [%4];"
                 : "=r"(r[0]), "=r"(r[1]), "=r"(r[2]), "=r"(r[3]) : "r"(addr));
}
DI void mma16(float (&d)[4], const uint32_t (&a)[4], uint32_t b0, uint32_t b1) {
    asm volatile("mma.sync.aligned.m16n8k16.row.col.f32.f16.f16.f32 "
                 "{%0,%1,%2,%3}, {%4,%5,%6,%7}, {%8,%9}, {%0,%1,%2,%3};"
                 : "+f"(d[0]), "+f"(d[1]), "+f"(d[2]), "+f"(d[3])
                 : "r"(a[0]), "r"(a[1]), "r"(a[2]), "r"(a[3]), "r"(b0), "r"(b1));
}
DI void cp16(uint32_t dst, const void* src) {
    asm volatile("cp.async.cg.shared.global [%0], [%1], 16;" :: "r"(dst), "l"(src) : "memory");
}
#define CP_COMMIT() asm volatile("cp.async.commit_group;" ::: "memory")
#define CP_WAIT0()  asm volatile("cp.async.wait_group 0;" ::: "memory")

// ---------------- kernel 1: transpose + fp16-round fc_w (tiny) -------------
__global__ void wt_kernel(const float* __restrict__ w) {
    __shared__ float t[32][33];
    int k0 = blockIdx.x * 32, n0 = blockIdx.y * 32;
    int x = threadIdx.x, y = threadIdx.y;
    #pragma unroll
    for (int dy = 0; dy < 32; dy += 8)
        t[y + dy][x] = w[(size_t)(k0 + y + dy) * NDIM + n0 + x];
    __syncthreads();
    #pragma unroll
    for (int dy = 0; dy < 32; dy += 8)
        g_wth[(size_t)(n0 + y + dy) * KDIM + k0 + x] = __float2half_rn(t[x][y + dy]);
}

// ---------------- kernel 2: fused-cvt fp16 GEMM; loaders own A and B -------
// Loader chunk work (~1100 cyc < 2048 cyc compute window):
//   1) issue B cp.async (2048 x 16B slots / 128 thr = 16 each)
//   2) A: 16 LDG.128 f32 -> cvt f16 -> 8 STS.128 (1024 slots / 128 thr)
//   3) wait_group 0 (B resident), then chunk barrier
DI void loader_fill(const float* __restrict__ swin, char* smem_c, uint32_t sb,
                    int m0, int gn0, int chunk, int lt) {
    uint32_t bb = sb + SM_B0 + (chunk & 1) * B_STAGE;
    const __half* bsrc = g_wth + (size_t)gn0 * KDIM + chunk * KC;
    #pragma unroll
    for (int s = 0; s < 16; s++) {
        int slot = lt + s * 128;
        int row = slot >> 3, q = slot & 7;
        cp16(bb + row * 128 + (((uint32_t)q ^ (row & 7)) << 4),
             bsrc + (size_t)row * KDIM + q * 8);
    }
    CP_COMMIT();
    char* abuf = smem_c + (chunk & 1) * A_STAGE;
    const float* asrc = swin + (size_t)m0 * KDIM + chunk * KC;
    #pragma unroll
    for (int s = 0; s < 8; s++) {
        int slot = lt + s * 128;
        int row = slot >> 3, q = slot & 7;
        const float* p = asrc + (size_t)row * KDIM + q * 8;
        float4 v0 = *(const float4*)p;
        float4 v1 = *(const float4*)(p + 4);
        __half2 h0 = __floats2half2_rn(v0.x, v0.y);
        __half2 h1 = __floats2half2_rn(v0.z, v0.w);
        __half2 h2 = __floats2half2_rn(v1.x, v1.y);
        __half2 h3 = __floats2half2_rn(v1.z, v1.w);
        uint4 o;
        o.x = *(uint32_t*)&h0; o.y = *(uint32_t*)&h1;
        o.z = *(uint32_t*)&h2; o.w = *(uint32_t*)&h3;
        *(uint4*)(abuf + row * 128 + (((uint32_t)q ^ (row & 7)) << 4)) = o;
    }
    CP_WAIT0();                              // B chunk resident
}

__global__ void __launch_bounds__(NTHR, 1)
gemm_kernel(const float* __restrict__ swin, const float* __restrict__ fcb) {
    extern __shared__ char smem[];
    uint32_t sb = smem_u32(smem);
    int tid = threadIdx.x;
    int w = tid >> 5, l = tid & 31;
    bool is_comp = tid < NCOMP;
    int lt = tid - NCOMP;                    // loader lane 0..127
    int nb = blockIdx.x;
    int m0 = blockIdx.y * M_TILE;
    int gn0 = nb * N_TILE;
    int wm = (w >> 2) * 64;                  // warp m offset (0,64)
    int wn = (w & 3) * 64;                   // warp n offset (0,64,128,192)

    if (tid < N_TILE) *(float*)(smem + SM_BIAS + tid * 4) = fcb[gn0 + tid];

    // ---- prologue: chunk 0 ----
    if (!is_comp)
        loader_fill(swin, smem, sb, m0, gn0, 0, lt);
    __syncthreads();

    if (!is_comp) {
        // loader loop: during compute of chunk i, produce chunk i+1
        for (int i = 0; i < NK; i++) {
            if (i + 1 < NK)
                loader_fill(swin, smem, sb, m0, gn0, i + 1, lt);
            __syncthreads();                 // chunk boundary
        }
        return;                              // sm_70+: exited threads don't block barriers
    }

    // ---- compute warps: pure ldsm/mma loop ----
    float acc[4][8][4];
    #pragma unroll
    for (int mt = 0; mt < 4; mt++)
        #pragma unroll
        for (int nt = 0; nt < 8; nt++)
            #pragma unroll
            for (int j = 0; j < 4; j++) acc[mt][nt][j] = 0.f;

    // per-lane ldmatrix offsets (verified mapping)
    uint32_t lx   = (uint32_t)(l & 7);
    uint32_t apar = (uint32_t)(l >> 4);          // A k-half parity
    uint32_t bpar = (uint32_t)((l >> 3) & 1);    // B k-half parity
    uint32_t a_off[4], b_off[4];
    {
        uint32_t arow = (uint32_t)(wm + (l & 15));
        #pragma unroll
        for (int mt = 0; mt < 4; mt++) a_off[mt] = (arow + mt * 16) * 128u;
        uint32_t brow = (uint32_t)(wn + (l & 7) + ((l & 16) >> 1));
        #pragma unroll
        for (int g = 0; g < 4; g++) b_off[g] = (brow + g * 16) * 128u + SM_B0;
    }

    for (int i = 0; i < NK; i++) {
        uint32_t ab = sb + ((uint32_t)i & 1) * A_STAGE;
        uint32_t bsel = ((uint32_t)i & 1) * B_STAGE;
        #pragma unroll
        for (int ks = 0; ks < 4; ks++) {
            uint32_t ca = ((2u * ks + apar) ^ lx) << 4;
            uint32_t cb = ((2u * ks + bpar) ^ lx) << 4;
            uint32_t bfr[4][4];
            #pragma unroll
            for (int g = 0; g < 4; g++) ldsm4(bfr[g], sb + bsel + b_off[g] + cb);
            #pragma unroll
            for (int mt = 0; mt < 4; mt++) {
                uint32_t af[4];
                ldsm4(af, ab + a_off[mt] + ca);
                #pragma unroll
                for (int nt = 0; nt < 8; nt++)
                    mma16(acc[mt][nt], af,
                          bfr[nt >> 1][(nt & 1) * 2], bfr[nt >> 1][(nt & 1) * 2 + 1]);
            }
        }
        __syncthreads();                     // chunk boundary (pairs with loader)
    }

    // ---- epilogue: bias, fp16 vid write, per-row sumsq ----
    const float* sbias = (const float*)(smem + SM_BIAS);
    float* part = (float*)smem;              // [128][4] (post-barrier reuse)
    #pragma unroll
    for (int mt = 0; mt < 4; mt++) {
        int r0 = wm + mt * 16 + (l >> 2);
        float s0 = 0.f, s1 = 0.f;
        #pragma unroll
        for (int nt = 0; nt < 8; nt++) {
            int colL = wn + nt * 8 + (l & 3) * 2;
            float b0 = sbias[colL], b1 = sbias[colL + 1];
            float v0 = acc[mt][nt][0] + b0, v1 = acc[mt][nt][1] + b1;
            float v2 = acc[mt][nt][2] + b0, v3 = acc[mt][nt][3] + b1;
            s0 += v0 * v0 + v1 * v1;
            s1 += v2 * v2 + v3 * v3;
            size_t g0 = (size_t)(m0 + r0) * NDIM + gn0 + colL;
            *(__half2*)(g_vid + g0) = __floats2half2_rn(v0, v1);
            *(__half2*)(g_vid + g0 + 8 * NDIM) = __floats2half2_rn(v2, v3);
        }
        s0 += __shfl_xor_sync(0xFFFFFFFFu, s0, 1);
        s0 += __shfl_xor_sync(0xFFFFFFFFu, s0, 2);
        s1 += __shfl_xor_sync(0xFFFFFFFFu, s1, 1);
        s1 += __shfl_xor_sync(0xFFFFFFFFu, s1, 2);
        if ((l & 3) == 0) {
            part[r0 * 4 + (w & 3)] = s0;
            part[(r0 + 8) * 4 + (w & 3)] = s1;
        }
    }
    __syncthreads();
    if (tid < M_TILE) {
        float s = part[tid * 4] + part[tid * 4 + 1] + part[tid * 4 + 2] + part[tid * 4 + 3];
        g_part[nb][m0 + tid] = s;
    }
}

// ---------------- kernel 3: token/frame scores + gumbel selection ----------
__global__ void select_kernel(const float* __restrict__ tscore,
                              const float* __restrict__ gumbel,
                              float* __restrict__ out, long long out_elems) {
    __shared__ float tsh[TOK];
    __shared__ float fsh[NFRM];
    __shared__ float gsh[NSEL * NFRM];
    int b = blockIdx.x, t = threadIdx.x;     // 256 threads
    for (int i = t; i < TOK; i += 256) {
        int gt = b * TOK + i;
        float s = g_part[0][gt] + g_part[1][gt];
        tsh[i] = tscore[gt] * sqrtf(s);
    }
    if (t < NSEL * NFRM) {
        int s = t >> 4, f = t & 15;
        gsh[t] = gumbel[((size_t)s * BATCH + b) * NFRM + f];
    }
    __syncthreads();
    if (t < NFRM) {
        float s = 0.f;
        #pragma unroll
        for (int j = 0; j < TPF; j++) s += tsh[t * TPF + j];
        fsh[t] = s;
    }
    __syncthreads();
    if (t == 0) {
        const float NEG_INF = __int_as_float(0xff800000);
        float tot = 0.f;
        for (int f = 0; f < NFRM; f++) tot += fsh[f];
        float fs[NFRM], sc[NFRM], sel[NFRM];
        for (int f = 0; f < NFRM; f++) { fs[f] = fsh[f] / tot; sc[f] = fs[f]; sel[f] = 0.f; }
        for (int s = 0; s < NSEL; s++) {
            const float* g = gsh + s * NFRM;
            float best = NEG_INF; int bi = 0;
            for (int f = 0; f < NFRM; f++) {
                float v = (sel[f] > 0.f) ? NEG_INF : (sc[f] + g[f]);
                if (v > best) { best = v; bi = f; }   // strict > == first-max argmax
            }
            sel[bi] = 1.f; sc[bi] = 0.f;
        }
        float rest = 0.f;
        for (int f = 0; f < NFRM; f++) rest += fs[f] * (1.f - sel[f]);
        float label = (rest >= 0.5f) ? 1.f : 0.f;
        int c = 0;
        for (int f = 0; f < NFRM; f++)
            if (sel[f] > 0.f) g_sel[b * NSEL + (c++)] = f;     // ascending
        if (out_elems >= SEL_ELEMS + BATCH + (long long)BATCH * NFRM) {
            out[SEL_ELEMS + b] = label;
            float* fsp = out + SEL_ELEMS + BATCH;
            for (int f = 0; f < NFRM; f++) fsp[b * NFRM + f] = sel[f];
        }
    }
}

// ---------------- kernel 4: gather selected frames (f16 -> f32) ------------
__global__ void gather_kernel(float* __restrict__ out) {
    int j = blockIdx.x, b = blockIdx.y;
    int f = g_sel[b * NSEL + j];
    const __half* src = g_vid + ((size_t)b * TOK + (size_t)f * TPF) * NDIM;
    float* dst = out + ((size_t)b * (NSEL * TPF) + (size_t)j * TPF) * NDIM;
    constexpr int N8 = TPF * NDIM / 8;       // 3136 groups of 8 halves
    for (int i = threadIdx.x; i < N8; i += blockDim.x) {
        uint4 h = *(const uint4*)(src + (size_t)i * 8);
        __half2 h0 = *(__half2*)&h.x, h1 = *(__half2*)&h.y;
        __half2 h2 = *(__half2*)&h.z, h3 = *(__half2*)&h.w;
        float2 f0 = __half22float2(h0), f1 = __half22float2(h1);
        float2 f2 = __half22float2(h2), f3 = __half22float2(h3);
        *(float4*)(dst + (size_t)i * 8)     = make_float4(f0.x, f0.y, f1.x, f1.y);
        *(float4*)(dst + (size_t)i * 8 + 4) = make_float4(f2.x, f2.y, f3.x, f3.y);
    }
}

// ---------------- launch ----------------
extern "C" void kernel_launch(void* const* d_in, const int* in_sizes, int n_in,
                              void* d_out, int out_size) {
    const float* swin = (const float*)d_in[0];   // (128, 784, 1024)
    const float* fcw  = (const float*)d_in[1];   // (1024, 512)
    const float* fcb  = (const float*)d_in[2];   // (512,)
    const float* tsc  = (const float*)d_in[3];   // (128, 784)
    const float* gum  = (const float*)d_in[4];   // (8, 128, 16)
    float* out = (float*)d_out;

    cudaFuncSetAttribute(gemm_kernel, cudaFuncAttributeMaxDynamicSharedMemorySize, SM_TOTAL);

    wt_kernel<<<dim3(KDIM / 32, NDIM / 32), dim3(32, 8)>>>(fcw);
    gemm_kernel<<<dim3(NDIM / N_TILE, MTOT / M_TILE), NTHR, SM_TOTAL>>>(swin, fcb);
    select_kernel<<<BATCH, 256>>>(tsc, gum, out, (long long)out_size);
    gather_kernel<<<dim3(NSEL, BATCH), 256>>>(out);
    (void)in_sizes; (void)n_in;
}

// round 13
// speedup vs baseline: 1.2406x; 1.0176x over previous
#include <cuda_runtime.h>
#include <cuda_fp16.h>
#include <cstdint>

#define DI __device__ __forceinline__

// ---------------- problem constants ----------------
namespace {
constexpr int BATCH = 128;
constexpr int NFRM  = 16;
constexpr int TPF   = 49;
constexpr int NSEL  = 8;
constexpr int TOK   = NFRM * TPF;          // 784
constexpr int MTOT  = BATCH * TOK;         // 100352
constexpr int KDIM  = 1024;
constexpr int NDIM  = 512;

constexpr int M_TILE = 128;
constexpr int N_TILE = 256;
constexpr int KC     = 64;                 // fp16 elems per K-chunk (=128B row)
constexpr int NK     = KDIM / KC;          // 16
constexpr int NCOMP  = 256;                // 8 compute warps: 2(m) x 4(n), 64x64
constexpr int NTHR   = 384;                // + 4 loader warps (128 threads)
constexpr long long SEL_ELEMS = (long long)BATCH * NSEL * TPF * NDIM; // 25,690,112

// shared memory: 2 A stages (16KB), 2 B stages (32KB), bias
constexpr int A_STAGE  = 16384;
constexpr int SM_B0    = 2 * A_STAGE;      // 32768
constexpr int B_STAGE  = 32768;
constexpr int SM_BIAS  = SM_B0 + 2 * B_STAGE;   // 98304
constexpr int SM_TOTAL = SM_BIAS + 1024;        // 99328

constexpr int GATHER_SPLIT = 4;            // CTAs per frame in gather
}

// ---------------- device scratch (no runtime allocation allowed) -----------
__device__ __half g_vid[(size_t)MTOT * NDIM];    // 102.8 MB vid_feats (fp16)
__device__ __half g_wth[NDIM * KDIM];            // fc_w transposed, fp16
__device__ float  g_part[2][MTOT];               // per-n-block sumsq partials
__device__ int    g_sel[BATCH * NSEL];           // selected frames, ascending

// ---------------- PTX helpers ----------------
DI uint32_t smem_u32(const void* p) {
    uint32_t a;
    asm("{ .reg .u64 t; cvta.to.shared.u64 t, %1; cvt.u32.u64 %0, t; }" : "=r"(a) : "l"(p));
    return a;
}
DI void ldsm4(uint32_t (&r)[4], uint32_t addr) {
    asm volatile("ldmatrix.sync.aligned.m8n8.x4.shared.b16 {%0,%1,%2,%3}, [%4];"
                 : "=r"(r[0]), "=r"(r[1]), "=r"(r[2]), "=r"(r[3]) : "r"(addr));
}
DI void mma16(float (&d)[4], const uint32_t (&a)[4], uint32_t b0, uint32_t b1) {
    asm volatile("mma.sync.aligned.m16n8k16.row.col.f32.f16.f16.f32 "
                 "{%0,%1,%2,%3}, {%4,%5,%6,%7}, {%8,%9}, {%0,%1,%2,%3};"
                 : "+f"(d[0]), "+f"(d[1]), "+f"(d[2]), "+f"(d[3])
                 : "r"(a[0]), "r"(a[1]), "r"(a[2]), "r"(a[3]), "r"(b0), "r"(b1));
}
DI void cp16(uint32_t dst, const void* src) {
    asm volatile("cp.async.cg.shared.global [%0], [%1], 16;" :: "r"(dst), "l"(src) : "memory");
}
#define CP_COMMIT() asm volatile("cp.async.commit_group;" ::: "memory")
#define CP_WAIT0()  asm volatile("cp.async.wait_group 0;" ::: "memory")

// ---------------- kernel 1: transpose + fp16-round fc_w (tiny) -------------
__global__ void wt_kernel(const float* __restrict__ w) {
    __shared__ float t[32][33];
    int k0 = blockIdx.x * 32, n0 = blockIdx.y * 32;
    int x = threadIdx.x, y = threadIdx.y;
    #pragma unroll
    for (int dy = 0; dy < 32; dy += 8)
        t[y + dy][x] = w[(size_t)(k0 + y + dy) * NDIM + n0 + x];
    __syncthreads();
    #pragma unroll
    for (int dy = 0; dy < 32; dy += 8)
        g_wth[(size_t)(n0 + y + dy) * KDIM + k0 + x] = __float2half_rn(t[x][y + dy]);
}

// ---------------- kernel 2: fused-cvt fp16 GEMM; loaders own A and B -------
// Loader chunk work (~1100 cyc < 2048 cyc compute window):
//   1) issue B cp.async (2048 x 16B slots / 128 thr = 16 each)
//   2) A: 16 LDG.128 f32 -> cvt f16 -> 8 STS.128 (1024 slots / 128 thr)
//   3) wait_group 0 (B resident), then chunk barrier
DI void loader_fill(const float* __restrict__ swin, char* smem_c, uint32_t sb,
                    int m0, int gn0, int chunk, int lt) {
    uint32_t bb = sb + SM_B0 + (chunk & 1) * B_STAGE;
    const __half* bsrc = g_wth + (size_t)gn0 * KDIM + chunk * KC;
    #pragma unroll
    for (int s = 0; s < 16; s++) {
        int slot = lt + s * 128;
        int row = slot >> 3, q = slot & 7;
        cp16(bb + row * 128 + (((uint32_t)q ^ (row & 7)) << 4),
             bsrc + (size_t)row * KDIM + q * 8);
    }
    CP_COMMIT();
    char* abuf = smem_c + (chunk & 1) * A_STAGE;
    const float* asrc = swin + (size_t)m0 * KDIM + chunk * KC;
    #pragma unroll
    for (int s = 0; s < 8; s++) {
        int slot = lt + s * 128;
        int row = slot >> 3, q = slot & 7;
        const float* p = asrc + (size_t)row * KDIM + q * 8;
        float4 v0 = *(const float4*)p;
        float4 v1 = *(const float4*)(p + 4);
        __half2 h0 = __floats2half2_rn(v0.x, v0.y);
        __half2 h1 = __floats2half2_rn(v0.z, v0.w);
        __half2 h2 = __floats2half2_rn(v1.x, v1.y);
        __half2 h3 = __floats2half2_rn(v1.z, v1.w);
        uint4 o;
        o.x = *(uint32_t*)&h0; o.y = *(uint32_t*)&h1;
        o.z = *(uint32_t*)&h2; o.w = *(uint32_t*)&h3;
        *(uint4*)(abuf + row * 128 + (((uint32_t)q ^ (row & 7)) << 4)) = o;
    }
    CP_WAIT0();                              // B chunk resident
}

__global__ void __launch_bounds__(NTHR, 1)
gemm_kernel(const float* __restrict__ swin, const float* __restrict__ fcb) {
    extern __shared__ char smem[];
    uint32_t sb = smem_u32(smem);
    int tid = threadIdx.x;
    int w = tid >> 5, l = tid & 31;
    bool is_comp = tid < NCOMP;
    int lt = tid - NCOMP;                    // loader lane 0..127
    int nb = blockIdx.x;
    int m0 = blockIdx.y * M_TILE;
    int gn0 = nb * N_TILE;
    int wm = (w >> 2) * 64;                  // warp m offset (0,64)
    int wn = (w & 3) * 64;                   // warp n offset (0,64,128,192)

    if (tid < N_TILE) *(float*)(smem + SM_BIAS + tid * 4) = fcb[gn0 + tid];

    // ---- prologue: chunk 0 ----
    if (!is_comp)
        loader_fill(swin, smem, sb, m0, gn0, 0, lt);
    __syncthreads();

    if (!is_comp) {
        // loader loop: during compute of chunk i, produce chunk i+1
        for (int i = 0; i < NK; i++) {
            if (i + 1 < NK)
                loader_fill(swin, smem, sb, m0, gn0, i + 1, lt);
            __syncthreads();                 // chunk boundary
        }
        return;                              // sm_70+: exited threads don't block barriers
    }

    // ---- compute warps: pure ldsm/mma loop ----
    float acc[4][8][4];
    #pragma unroll
    for (int mt = 0; mt < 4; mt++)
        #pragma unroll
        for (int nt = 0; nt < 8; nt++)
            #pragma unroll
            for (int j = 0; j < 4; j++) acc[mt][nt][j] = 0.f;

    // per-lane ldmatrix offsets (verified mapping)
    uint32_t lx   = (uint32_t)(l & 7);
    uint32_t apar = (uint32_t)(l >> 4);          // A k-half parity
    uint32_t bpar = (uint32_t)((l >> 3) & 1);    // B k-half parity
    uint32_t a_off[4], b_off[4];
    {
        uint32_t arow = (uint32_t)(wm + (l & 15));
        #pragma unroll
        for (int mt = 0; mt < 4; mt++) a_off[mt] = (arow + mt * 16) * 128u;
        uint32_t brow = (uint32_t)(wn + (l & 7) + ((l & 16) >> 1));
        #pragma unroll
        for (int g = 0; g < 4; g++) b_off[g] = (brow + g * 16) * 128u + SM_B0;
    }

    for (int i = 0; i < NK; i++) {
        uint32_t ab = sb + ((uint32_t)i & 1) * A_STAGE;
        uint32_t bsel = ((uint32_t)i & 1) * B_STAGE;
        #pragma unroll
        for (int ks = 0; ks < 4; ks++) {
            uint32_t ca = ((2u * ks + apar) ^ lx) << 4;
            uint32_t cb = ((2u * ks + bpar) ^ lx) << 4;
            uint32_t bfr[4][4];
            #pragma unroll
            for (int g = 0; g < 4; g++) ldsm4(bfr[g], sb + bsel + b_off[g] + cb);
            #pragma unroll
            for (int mt = 0; mt < 4; mt++) {
                uint32_t af[4];
                ldsm4(af, ab + a_off[mt] + ca);
                #pragma unroll
                for (int nt = 0; nt < 8; nt++)
                    mma16(acc[mt][nt], af,
                          bfr[nt >> 1][(nt & 1) * 2], bfr[nt >> 1][(nt & 1) * 2 + 1]);
            }
        }
        __syncthreads();                     // chunk boundary (pairs with loader)
    }

    // ---- epilogue: bias, fp16 vid write, per-row sumsq ----
    const float* sbias = (const float*)(smem + SM_BIAS);
    float* part = (float*)smem;              // [128][4] (post-barrier reuse)
    #pragma unroll
    for (int mt = 0; mt < 4; mt++) {
        int r0 = wm + mt * 16 + (l >> 2);
        float s0 = 0.f, s1 = 0.f;
        #pragma unroll
        for (int nt = 0; nt < 8; nt++) {
            int colL = wn + nt * 8 + (l & 3) * 2;
            float b0 = sbias[colL], b1 = sbias[colL + 1];
            float v0 = acc[mt][nt][0] + b0, v1 = acc[mt][nt][1] + b1;
            float v2 = acc[mt][nt][2] + b0, v3 = acc[mt][nt][3] + b1;
            s0 += v0 * v0 + v1 * v1;
            s1 += v2 * v2 + v3 * v3;
            size_t g0 = (size_t)(m0 + r0) * NDIM + gn0 + colL;
            *(__half2*)(g_vid + g0) = __floats2half2_rn(v0, v1);
            *(__half2*)(g_vid + g0 + 8 * NDIM) = __floats2half2_rn(v2, v3);
        }
        s0 += __shfl_xor_sync(0xFFFFFFFFu, s0, 1);
        s0 += __shfl_xor_sync(0xFFFFFFFFu, s0, 2);
        s1 += __shfl_xor_sync(0xFFFFFFFFu, s1, 1);
        s1 += __shfl_xor_sync(0xFFFFFFFFu, s1, 2);
        if ((l & 3) == 0) {
            part[r0 * 4 + (w & 3)] = s0;
            part[(r0 + 8) * 4 + (w & 3)] = s1;
        }
    }
    __syncthreads();
    if (tid < M_TILE) {
        float s = part[tid * 4] + part[tid * 4 + 1] + part[tid * 4 + 2] + part[tid * 4 + 3];
        g_part[nb][m0 + tid] = s;
    }
}

// ---------------- kernel 3: token/frame scores + gumbel selection ----------
__global__ void select_kernel(const float* __restrict__ tscore,
                              const float* __restrict__ gumbel,
                              float* __restrict__ out, long long out_elems) {
    __shared__ float tsh[TOK];
    __shared__ float fsh[NFRM];
    __shared__ float gsh[NSEL * NFRM];
    int b = blockIdx.x, t = threadIdx.x;     // 256 threads
    for (int i = t; i < TOK; i += 256) {
        int gt = b * TOK + i;
        float s = g_part[0][gt] + g_part[1][gt];
        tsh[i] = tscore[gt] * sqrtf(s);
    }
    if (t < NSEL * NFRM) {
        int s = t >> 4, f = t & 15;
        gsh[t] = gumbel[((size_t)s * BATCH + b) * NFRM + f];
    }
    __syncthreads();
    if (t < NFRM) {
        float s = 0.f;
        #pragma unroll
        for (int j = 0; j < TPF; j++) s += tsh[t * TPF + j];
        fsh[t] = s;
    }
    __syncthreads();
    if (t == 0) {
        const float NEG_INF = __int_as_float(0xff800000);
        float tot = 0.f;
        for (int f = 0; f < NFRM; f++) tot += fsh[f];
        float fs[NFRM], sc[NFRM], sel[NFRM];
        for (int f = 0; f < NFRM; f++) { fs[f] = fsh[f] / tot; sc[f] = fs[f]; sel[f] = 0.f; }
        for (int s = 0; s < NSEL; s++) {
            const float* g = gsh + s * NFRM;
            float best = NEG_INF; int bi = 0;
            for (int f = 0; f < NFRM; f++) {
                float v = (sel[f] > 0.f) ? NEG_INF : (sc[f] + g[f]);
                if (v > best) { best = v; bi = f; }   // strict > == first-max argmax
            }
            sel[bi] = 1.f; sc[bi] = 0.f;
        }
        float rest = 0.f;
        for (int f = 0; f < NFRM; f++) rest += fs[f] * (1.f - sel[f]);
        float label = (rest >= 0.5f) ? 1.f : 0.f;
        int c = 0;
        for (int f = 0; f < NFRM; f++)
            if (sel[f] > 0.f) g_sel[b * NSEL + (c++)] = f;     // ascending
        if (out_elems >= SEL_ELEMS + BATCH + (long long)BATCH * NFRM) {
            out[SEL_ELEMS + b] = label;
            float* fsp = out + SEL_ELEMS + BATCH;
            for (int f = 0; f < NFRM; f++) fsp[b * NFRM + f] = sel[f];
        }
    }
}

// ---------------- kernel 4: gather selected frames (f16 -> f32) ------------
// grid (NSEL*GATHER_SPLIT, BATCH): each CTA moves a quarter frame (25KB)
__global__ void gather_kernel(float* __restrict__ out) {
    int j = blockIdx.x / GATHER_SPLIT;       // selected slot 0..7
    int part = blockIdx.x % GATHER_SPLIT;    // quarter 0..3
    int b = blockIdx.y;
    int f = g_sel[b * NSEL + j];
    constexpr int N8 = TPF * NDIM / 8;       // 3136 groups of 8 halves per frame
    constexpr int Q  = N8 / GATHER_SPLIT;    // 784 groups per CTA
    const __half* src = g_vid + ((size_t)b * TOK + (size_t)f * TPF) * NDIM
                      + (size_t)part * Q * 8;
    float* dst = out + ((size_t)b * (NSEL * TPF) + (size_t)j * TPF) * NDIM
               + (size_t)part * Q * 8;
    for (int i = threadIdx.x; i < Q; i += 256) {
        uint4 h = *(const uint4*)(src + (size_t)i * 8);
        __half2 h0 = *(__half2*)&h.x, h1 = *(__half2*)&h.y;
        __half2 h2 = *(__half2*)&h.z, h3 = *(__half2*)&h.w;
        float2 f0 = __half22float2(h0), f1 = __half22float2(h1);
        float2 f2 = __half22float2(h2), f3 = __half22float2(h3);
        *(float4*)(dst + (size_t)i * 8)     = make_float4(f0.x, f0.y, f1.x, f1.y);
        *(float4*)(dst + (size_t)i * 8 + 4) = make_float4(f2.x, f2.y, f3.x, f3.y);
    }
}

// ---------------- launch ----------------
extern "C" void kernel_launch(void* const* d_in, const int* in_sizes, int n_in,
                              void* d_out, int out_size) {
    const float* swin = (const float*)d_in[0];   // (128, 784, 1024)
    const float* fcw  = (const float*)d_in[1];   // (1024, 512)
    const float* fcb  = (const float*)d_in[2];   // (512,)
    const float* tsc  = (const float*)d_in[3];   // (128, 784)
    const float* gum  = (const float*)d_in[4];   // (8, 128, 16)
    float* out = (float*)d_out;

    cudaFuncSetAttribute(gemm_kernel, cudaFuncAttributeMaxDynamicSharedMemorySize, SM_TOTAL);

    wt_kernel<<<dim3(KDIM / 32, NDIM / 32), dim3(32, 8)>>>(fcw);
    gemm_kernel<<<dim3(NDIM / N_TILE, MTOT / M_TILE), NTHR, SM_TOTAL>>>(swin, fcb);
    select_kernel<<<BATCH, 256>>>(tsc, gum, out, (long long)out_size);
    gather_kernel<<<dim3(NSEL * GATHER_SPLIT, BATCH), 256>>>(out);
    (void)in_sizes; (void)n_in;
}

// round 14
// speedup vs baseline: 1.2478x; 1.0058x over previous
#include <cuda_runtime.h>
#include <cuda_fp16.h>
#include <cstdint>

#define DI __device__ __forceinline__

// ---------------- problem constants ----------------
namespace {
constexpr int BATCH = 128;
constexpr int NFRM  = 16;
constexpr int TPF   = 49;
constexpr int NSEL  = 8;
constexpr int TOK   = NFRM * TPF;          // 784
constexpr int MTOT  = BATCH * TOK;         // 100352
constexpr int KDIM  = 1024;
constexpr int NDIM  = 512;

constexpr int M_TILE = 128;
constexpr int N_TILE = 256;
constexpr int KC     = 64;                 // fp16 elems per K-chunk (=128B row)
constexpr int NK     = KDIM / KC;          // 16
constexpr int NCOMP  = 256;                // 8 compute warps: 2(m) x 4(n), 64x64
constexpr int NTHR   = 384;                // + 4 loader warps (128 threads)
constexpr long long SEL_ELEMS = (long long)BATCH * NSEL * TPF * NDIM; // 25,690,112

// shared memory: 2 A stages (16KB), 2 B stages (32KB), bias
constexpr int A_STAGE  = 16384;
constexpr int SM_B0    = 2 * A_STAGE;      // 32768
constexpr int B_STAGE  = 32768;
constexpr int SM_BIAS  = SM_B0 + 2 * B_STAGE;   // 98304
constexpr int SM_TOTAL = SM_BIAS + 1024;        // 99328

constexpr int GATHER_SPLIT = 4;            // CTAs per frame in gather
}

// ---------------- device scratch (no runtime allocation allowed) -----------
__device__ __half g_vid[(size_t)MTOT * NDIM];    // 102.8 MB vid_feats (fp16)
__device__ __half g_wth[NDIM * KDIM];            // fc_w transposed, fp16
__device__ float  g_part[2][MTOT];               // per-n-block sumsq partials
__device__ int    g_sel[BATCH * NSEL];           // selected frames, ascending

// ---------------- PTX helpers ----------------
DI uint32_t smem_u32(const void* p) {
    uint32_t a;
    asm("{ .reg .u64 t; cvta.to.shared.u64 t, %1; cvt.u32.u64 %0, t; }" : "=r"(a) : "l"(p));
    return a;
}
DI void ldsm4(uint32_t (&r)[4], uint32_t addr) {
    asm volatile("ldmatrix.sync.aligned.m8n8.x4.shared.b16 {%0,%1,%2,%3}, [%4];"
                 : "=r"(r[0]), "=r"(r[1]), "=r"(r[2]), "=r"(r[3]) : "r"(addr));
}
DI void mma16(float (&d)[4], const uint32_t (&a)[4], uint32_t b0, uint32_t b1) {
    asm volatile("mma.sync.aligned.m16n8k16.row.col.f32.f16.f16.f32 "
                 "{%0,%1,%2,%3}, {%4,%5,%6,%7}, {%8,%9}, {%0,%1,%2,%3};"
                 : "+f"(d[0]), "+f"(d[1]), "+f"(d[2]), "+f"(d[3])
                 : "r"(a[0]), "r"(a[1]), "r"(a[2]), "r"(a[3]), "r"(b0), "r"(b1));
}
DI void cp16(uint32_t dst, const void* src) {
    asm volatile("cp.async.cg.shared.global [%0], [%1], 16;" :: "r"(dst), "l"(src) : "memory");
}
#define CP_COMMIT() asm volatile("cp.async.commit_group;" ::: "memory")
#define CP_WAIT0()  asm volatile("cp.async.wait_group 0;" ::: "memory")

// ---------------- kernel 1: transpose + fp16-round fc_w (tiny) -------------
__global__ void wt_kernel(const float* __restrict__ w) {
    __shared__ float t[32][33];
    int k0 = blockIdx.x * 32, n0 = blockIdx.y * 32;
    int x = threadIdx.x, y = threadIdx.y;
    #pragma unroll
    for (int dy = 0; dy < 32; dy += 8)
        t[y + dy][x] = w[(size_t)(k0 + y + dy) * NDIM + n0 + x];
    __syncthreads();
    #pragma unroll
    for (int dy = 0; dy < 32; dy += 8)
        g_wth[(size_t)(n0 + y + dy) * KDIM + k0 + x] = __float2half_rn(t[x][y + dy]);
}

// ---------------- kernel 2: fused-cvt fp16 GEMM; loaders own A and B -------
// Loader chunk work (~1100 cyc < 2048 cyc compute window):
//   1) issue B cp.async (2048 x 16B slots / 128 thr = 16 each)
//   2) A: 16 LDG.128 f32 -> cvt f16 -> 8 STS.128 (1024 slots / 128 thr)
//   3) wait_group 0 (B resident), then chunk barrier
DI void loader_fill(const float* __restrict__ swin, char* smem_c, uint32_t sb,
                    int m0, int gn0, int chunk, int lt) {
    uint32_t bb = sb + SM_B0 + (chunk & 1) * B_STAGE;
    const __half* bsrc = g_wth + (size_t)gn0 * KDIM + chunk * KC;
    #pragma unroll
    for (int s = 0; s < 16; s++) {
        int slot = lt + s * 128;
        int row = slot >> 3, q = slot & 7;
        cp16(bb + row * 128 + (((uint32_t)q ^ (row & 7)) << 4),
             bsrc + (size_t)row * KDIM + q * 8);
    }
    CP_COMMIT();
    char* abuf = smem_c + (chunk & 1) * A_STAGE;
    const float* asrc = swin + (size_t)m0 * KDIM + chunk * KC;
    #pragma unroll
    for (int s = 0; s < 8; s++) {
        int slot = lt + s * 128;
        int row = slot >> 3, q = slot & 7;
        const float* p = asrc + (size_t)row * KDIM + q * 8;
        float4 v0 = *(const float4*)p;
        float4 v1 = *(const float4*)(p + 4);
        __half2 h0 = __floats2half2_rn(v0.x, v0.y);
        __half2 h1 = __floats2half2_rn(v0.z, v0.w);
        __half2 h2 = __floats2half2_rn(v1.x, v1.y);
        __half2 h3 = __floats2half2_rn(v1.z, v1.w);
        uint4 o;
        o.x = *(uint32_t*)&h0; o.y = *(uint32_t*)&h1;
        o.z = *(uint32_t*)&h2; o.w = *(uint32_t*)&h3;
        *(uint4*)(abuf + row * 128 + (((uint32_t)q ^ (row & 7)) << 4)) = o;
    }
    CP_WAIT0();                              // B chunk resident
}

__global__ void __launch_bounds__(NTHR, 1)
gemm_kernel(const float* __restrict__ swin, const float* __restrict__ fcb) {
    extern __shared__ char smem[];
    uint32_t sb = smem_u32(smem);
    int tid = threadIdx.x;
    int w = tid >> 5, l = tid & 31;
    bool is_comp = tid < NCOMP;
    int lt = tid - NCOMP;                    // loader lane 0..127
    int nb = blockIdx.x;
    int m0 = blockIdx.y * M_TILE;
    int gn0 = nb * N_TILE;
    int wm = (w >> 2) * 64;                  // warp m offset (0,64)
    int wn = (w & 3) * 64;                   // warp n offset (0,64,128,192)

    if (tid < N_TILE) *(float*)(smem + SM_BIAS + tid * 4) = fcb[gn0 + tid];

    // ---- prologue: chunk 0 ----
    if (!is_comp)
        loader_fill(swin, smem, sb, m0, gn0, 0, lt);
    __syncthreads();

    if (!is_comp) {
        // loader loop: during compute of chunk i, produce chunk i+1
        for (int i = 0; i < NK; i++) {
            if (i + 1 < NK)
                loader_fill(swin, smem, sb, m0, gn0, i + 1, lt);
            __syncthreads();                 // chunk boundary
        }
        return;                              // sm_70+: exited threads don't block barriers
    }

    // ---- compute warps: pure ldsm/mma loop ----
    float acc[4][8][4];
    #pragma unroll
    for (int mt = 0; mt < 4; mt++)
        #pragma unroll
        for (int nt = 0; nt < 8; nt++)
            #pragma unroll
            for (int j = 0; j < 4; j++) acc[mt][nt][j] = 0.f;

    // per-lane ldmatrix offsets (verified mapping)
    uint32_t lx   = (uint32_t)(l & 7);
    uint32_t apar = (uint32_t)(l >> 4);          // A k-half parity
    uint32_t bpar = (uint32_t)((l >> 3) & 1);    // B k-half parity
    uint32_t a_off[4], b_off[4];
    {
        uint32_t arow = (uint32_t)(wm + (l & 15));
        #pragma unroll
        for (int mt = 0; mt < 4; mt++) a_off[mt] = (arow + mt * 16) * 128u;
        uint32_t brow = (uint32_t)(wn + (l & 7) + ((l & 16) >> 1));
        #pragma unroll
        for (int g = 0; g < 4; g++) b_off[g] = (brow + g * 16) * 128u + SM_B0;
    }

    for (int i = 0; i < NK; i++) {
        uint32_t ab = sb + ((uint32_t)i & 1) * A_STAGE;
        uint32_t bsel = ((uint32_t)i & 1) * B_STAGE;
        #pragma unroll
        for (int ks = 0; ks < 4; ks++) {
            uint32_t ca = ((2u * ks + apar) ^ lx) << 4;
            uint32_t cb = ((2u * ks + bpar) ^ lx) << 4;
            uint32_t bfr[4][4];
            #pragma unroll
            for (int g = 0; g < 4; g++) ldsm4(bfr[g], sb + bsel + b_off[g] + cb);
            #pragma unroll
            for (int mt = 0; mt < 4; mt++) {
                uint32_t af[4];
                ldsm4(af, ab + a_off[mt] + ca);
                #pragma unroll
                for (int nt = 0; nt < 8; nt++)
                    mma16(acc[mt][nt], af,
                          bfr[nt >> 1][(nt & 1) * 2], bfr[nt >> 1][(nt & 1) * 2 + 1]);
            }
        }
        __syncthreads();                     // chunk boundary (pairs with loader)
    }

    // ---- epilogue: bias, fp16 vid write, per-row sumsq ----
    const float* sbias = (const float*)(smem + SM_BIAS);
    float* part = (float*)smem;              // [128][4] (post-barrier reuse)
    #pragma unroll
    for (int mt = 0; mt < 4; mt++) {
        int r0 = wm + mt * 16 + (l >> 2);
        float s0 = 0.f, s1 = 0.f;
        #pragma unroll
        for (int nt = 0; nt < 8; nt++) {
            int colL = wn + nt * 8 + (l & 3) * 2;
            float b0 = sbias[colL], b1 = sbias[colL + 1];
            float v0 = acc[mt][nt][0] + b0, v1 = acc[mt][nt][1] + b1;
            float v2 = acc[mt][nt][2] + b0, v3 = acc[mt][nt][3] + b1;
            s0 += v0 * v0 + v1 * v1;
            s1 += v2 * v2 + v3 * v3;
            size_t g0 = (size_t)(m0 + r0) * NDIM + gn0 + colL;
            *(__half2*)(g_vid + g0) = __floats2half2_rn(v0, v1);
            *(__half2*)(g_vid + g0 + 8 * NDIM) = __floats2half2_rn(v2, v3);
        }
        s0 += __shfl_xor_sync(0xFFFFFFFFu, s0, 1);
        s0 += __shfl_xor_sync(0xFFFFFFFFu, s0, 2);
        s1 += __shfl_xor_sync(0xFFFFFFFFu, s1, 1);
        s1 += __shfl_xor_sync(0xFFFFFFFFu, s1, 2);
        if ((l & 3) == 0) {
            part[r0 * 4 + (w & 3)] = s0;
            part[(r0 + 8) * 4 + (w & 3)] = s1;
        }
    }
    __syncthreads();
    if (tid < M_TILE) {
        float s = part[tid * 4] + part[tid * 4 + 1] + part[tid * 4 + 2] + part[tid * 4 + 3];
        g_part[nb][m0 + tid] = s;
    }
}

// ---------------- kernel 3: token/frame scores + gumbel selection ----------
__global__ void select_kernel(const float* __restrict__ tscore,
                              const float* __restrict__ gumbel,
                              float* __restrict__ out, long long out_elems) {
    __shared__ float tsh[TOK];
    __shared__ float fsh[NFRM];
    __shared__ float gsh[NSEL * NFRM];
    int b = blockIdx.x, t = threadIdx.x;     // 256 threads
    for (int i = t; i < TOK; i += 256) {
        int gt = b * TOK + i;
        float s = g_part[0][gt] + g_part[1][gt];
        tsh[i] = tscore[gt] * sqrtf(s);
    }
    if (t < NSEL * NFRM) {
        int s = t >> 4, f = t & 15;
        gsh[t] = gumbel[((size_t)s * BATCH + b) * NFRM + f];
    }
    __syncthreads();
    if (t < NFRM) {
        float s = 0.f;
        #pragma unroll
        for (int j = 0; j < TPF; j++) s += tsh[t * TPF + j];
        fsh[t] = s;
    }
    __syncthreads();
    if (t == 0) {
        const float NEG_INF = __int_as_float(0xff800000);
        float tot = 0.f;
        for (int f = 0; f < NFRM; f++) tot += fsh[f];
        float fs[NFRM], sc[NFRM], sel[NFRM];
        for (int f = 0; f < NFRM; f++) { fs[f] = fsh[f] / tot; sc[f] = fs[f]; sel[f] = 0.f; }
        for (int s = 0; s < NSEL; s++) {
            const float* g = gsh + s * NFRM;
            float best = NEG_INF; int bi = 0;
            for (int f = 0; f < NFRM; f++) {
                float v = (sel[f] > 0.f) ? NEG_INF : (sc[f] + g[f]);
                if (v > best) { best = v; bi = f; }   // strict > == first-max argmax
            }
            sel[bi] = 1.f; sc[bi] = 0.f;
        }
        float rest = 0.f;
        for (int f = 0; f < NFRM; f++) rest += fs[f] * (1.f - sel[f]);
        float label = (rest >= 0.5f) ? 1.f : 0.f;
        int c = 0;
        for (int f = 0; f < NFRM; f++)
            if (sel[f] > 0.f) g_sel[b * NSEL + (c++)] = f;     // ascending
        if (out_elems >= SEL_ELEMS + BATCH + (long long)BATCH * NFRM) {
            out[SEL_ELEMS + b] = label;
            float* fsp = out + SEL_ELEMS + BATCH;
            for (int f = 0; f < NFRM; f++) fsp[b * NFRM + f] = sel[f];
        }
    }
}

// ---------------- kernel 4: gather selected frames (f16 -> f32) ------------
// grid (NSEL*GATHER_SPLIT, BATCH); 2-deep unroll doubles per-thread MLP
__global__ void gather_kernel(float* __restrict__ out) {
    int j = blockIdx.x / GATHER_SPLIT;       // selected slot 0..7
    int part = blockIdx.x % GATHER_SPLIT;    // quarter 0..3
    int b = blockIdx.y;
    int f = g_sel[b * NSEL + j];
    constexpr int N8 = TPF * NDIM / 8;       // 3136 groups of 8 halves per frame
    constexpr int Q  = N8 / GATHER_SPLIT;    // 784 groups per CTA
    const __half* src = g_vid + ((size_t)b * TOK + (size_t)f * TPF) * NDIM
                      + (size_t)part * Q * 8;
    float* dst = out + ((size_t)b * (NSEL * TPF) + (size_t)j * TPF) * NDIM
               + (size_t)part * Q * 8;
    int t = threadIdx.x;                     // 256 threads
    for (int i = t; i < Q; i += 512) {
        int i2 = i + 256;
        bool have2 = (i2 < Q);
        uint4 ha = *(const uint4*)(src + (size_t)i * 8);
        uint4 hb = have2 ? *(const uint4*)(src + (size_t)i2 * 8) : ha;
        {
            __half2 h0 = *(__half2*)&ha.x, h1 = *(__half2*)&ha.y;
            __half2 h2 = *(__half2*)&ha.z, h3 = *(__half2*)&ha.w;
            float2 f0 = __half22float2(h0), f1 = __half22float2(h1);
            float2 f2 = __half22float2(h2), f3 = __half22float2(h3);
            *(float4*)(dst + (size_t)i * 8)     = make_float4(f0.x, f0.y, f1.x, f1.y);
            *(float4*)(dst + (size_t)i * 8 + 4) = make_float4(f2.x, f2.y, f3.x, f3.y);
        }
        if (have2) {
            __half2 h0 = *(__half2*)&hb.x, h1 = *(__half2*)&hb.y;
            __half2 h2 = *(__half2*)&hb.z, h3 = *(__half2*)&hb.w;
            float2 f0 = __half22float2(h0), f1 = __half22float2(h1);
            float2 f2 = __half22float2(h2), f3 = __half22float2(h3);
            *(float4*)(dst + (size_t)i2 * 8)     = make_float4(f0.x, f0.y, f1.x, f1.y);
            *(float4*)(dst + (size_t)i2 * 8 + 4) = make_float4(f2.x, f2.y, f3.x, f3.y);
        }
    }
}

// ---------------- launch ----------------
extern "C" void kernel_launch(void* const* d_in, const int* in_sizes, int n_in,
                              void* d_out, int out_size) {
    const float* swin = (const float*)d_in[0];   // (128, 784, 1024)
    const float* fcw  = (const float*)d_in[1];   // (1024, 512)
    const float* fcb  = (const float*)d_in[2];   // (512,)
    const float* tsc  = (const float*)d_in[3];   // (128, 784)
    const float* gum  = (const float*)d_in[4];   // (8, 128, 16)
    float* out = (float*)d_out;

    cudaFuncSetAttribute(gemm_kernel, cudaFuncAttributeMaxDynamicSharedMemorySize, SM_TOTAL);

    wt_kernel<<<dim3(KDIM / 32, NDIM / 32), dim3(32, 8)>>>(fcw);
    gemm_kernel<<<dim3(NDIM / N_TILE, MTOT / M_TILE), NTHR, SM_TOTAL>>>(swin, fcb);
    select_kernel<<<BATCH, 256>>>(tsc, gum, out, (long long)out_size);
    gather_kernel<<<dim3(NSEL * GATHER_SPLIT, BATCH), 256>>>(out);
    (void)in_sizes; (void)n_in;
}